// round 1
// baseline (speedup 1.0000x reference)
#include <cuda_runtime.h>
#include <cuda_bf16.h>
#include <cstdint>

#define EPS 1e-6f

// Shapes
#define B_ 4
#define N_ 8192
#define DIM_ 1024
#define H_ 16
#define DH_ 64
#define M_ (B_ * N_)            // 32768 rows
#define BIG (M_ * DIM_)         // 33554432 elems

// ---------------- scratch (static device globals; no allocation) ----------------
__device__ float g_q[BIG];
__device__ float g_k[BIG];
__device__ float g_v[BIG];
__device__ float g_qf[BIG];     // [bh, n, 64]
__device__ float g_kf[BIG];     // [bh, n, 64]
__device__ float g_attn[BIG];   // [b, n, 1024]
__device__ float g_kv[64 * 64 * 64];   // [bh, f, d]
__device__ float g_ksum[64 * 64];      // [bh, f]

// ---------------- generic tiled SGEMM: C = A[MxK] * B[KxN] (+bias) ----------------
// BM=BN=128, BK=16, 256 threads, 8x8 micro-tile. All dims divisible.
__global__ __launch_bounds__(256) void sgemm128(
    const float* __restrict__ A, const float* __restrict__ B,
    float* __restrict__ C, int M, int N, int K,
    const float* __restrict__ bias)
{
    __shared__ float As[16][128];
    __shared__ float Bs[16][128];

    const int tid  = threadIdx.x;
    const int brow = blockIdx.y;
    const int bcol = blockIdx.x;
    const int tx = tid % 16;      // col group
    const int ty = tid / 16;      // row group

    const float* Ab = A + (size_t)brow * 128 * K;
    const float* Bb = B + (size_t)bcol * 128;

    // A loads: 128x16 tile, 2048 floats, 2 float4/thread
    const int a_row = tid / 4;          // 0..63
    const int a_col = (tid % 4) * 4;    // 0..12
    // B loads: 16x128 tile, 2 float4/thread
    const int b_row = tid / 32;         // 0..7
    const int b_col = (tid % 32) * 4;   // 0..124

    float acc[8][8];
#pragma unroll
    for (int i = 0; i < 8; i++)
#pragma unroll
        for (int j = 0; j < 8; j++) acc[i][j] = 0.f;

    for (int k0 = 0; k0 < K; k0 += 16) {
#pragma unroll
        for (int s = 0; s < 2; s++) {
            float4 av = *(const float4*)(Ab + (size_t)(a_row + 64 * s) * K + k0 + a_col);
            As[a_col + 0][a_row + 64 * s] = av.x;
            As[a_col + 1][a_row + 64 * s] = av.y;
            As[a_col + 2][a_row + 64 * s] = av.z;
            As[a_col + 3][a_row + 64 * s] = av.w;
        }
#pragma unroll
        for (int s = 0; s < 2; s++) {
            float4 bv = *(const float4*)(Bb + (size_t)(k0 + b_row + 8 * s) * N + b_col);
            *(float4*)&Bs[b_row + 8 * s][b_col] = bv;
        }
        __syncthreads();

#pragma unroll
        for (int kk = 0; kk < 16; kk++) {
            float ar[8], br[8];
#pragma unroll
            for (int i = 0; i < 8; i++) ar[i] = As[kk][ty * 8 + i];
#pragma unroll
            for (int j = 0; j < 8; j++) br[j] = Bs[kk][tx * 8 + j];
#pragma unroll
            for (int i = 0; i < 8; i++)
#pragma unroll
                for (int j = 0; j < 8; j++)
                    acc[i][j] = fmaf(ar[i], br[j], acc[i][j]);
        }
        __syncthreads();
    }

#pragma unroll
    for (int i = 0; i < 8; i++) {
        size_t row = (size_t)brow * 128 + ty * 8 + i;
#pragma unroll
        for (int j = 0; j < 8; j += 4) {
            int col = bcol * 128 + tx * 8 + j;
            float4 o;
            o.x = acc[i][j + 0];
            o.y = acc[i][j + 1];
            o.z = acc[i][j + 2];
            o.w = acc[i][j + 3];
            if (bias) {
                o.x += bias[col + 0];
                o.y += bias[col + 1];
                o.z += bias[col + 2];
                o.w += bias[col + 3];
            }
            *(float4*)(C + row * N + col) = o;
        }
    }
}

// ---------------- feature map: outf[bh,n,f] = relu(inp[b,n,h*64+:] @ proj) + EPS ---
__global__ __launch_bounds__(256) void feature_map_kernel(
    const float* __restrict__ inp,   // [b, n, 1024]
    const float* __restrict__ proj,  // [64, 64]
    float* __restrict__ outf)        // [bh, n, 64]
{
    const int bh = blockIdx.y;       // 0..63
    const int b = bh / H_, h = bh % H_;
    const int n0 = blockIdx.x * 64;

    __shared__ float P[64 * 64];
    __shared__ float X[64][65];

    const int tid = threadIdx.x;
    for (int i = tid; i < 4096; i += 256) P[i] = proj[i];
    for (int i = tid; i < 4096; i += 256) {
        int r = i / 64, d = i % 64;
        X[r][d] = inp[((size_t)b * N_ + n0 + r) * DIM_ + h * DH_ + d];
    }
    __syncthreads();

    const int f = tid % 64;
    const int ry = tid / 64;  // 0..3
    for (int r = ry; r < 64; r += 4) {
        float s = 0.f;
#pragma unroll
        for (int d = 0; d < 64; d++) s = fmaf(X[r][d], P[d * 64 + f], s);
        s = fmaxf(s, 0.f) + EPS;
        outf[((size_t)bh * N_ + n0 + r) * 64 + f] = s;
    }
}

// ---------------- zero scratch ----------------
__global__ void zero_kv_kernel()
{
    int i = blockIdx.x * 256 + threadIdx.x;
    if (i < 64 * 64 * 64) g_kv[i] = 0.f;
    if (i < 64 * 64) g_ksum[i] = 0.f;
}

// ---------------- kv[f,d] += sum_n kf[n,f]*v[n,d]; ksum[f] += sum_n kf[n,f] -------
__global__ __launch_bounds__(256) void kv_accum_kernel(
    const float* __restrict__ kf,    // [bh, n, 64]
    const float* __restrict__ v)     // [b, n, 1024]
{
    const int bh = blockIdx.y;
    const int b = bh / H_, h = bh % H_;
    const int chunk = blockIdx.x;    // 16 chunks of 512 rows
    const int tid = threadIdx.x;

    __shared__ float kfs[2][64];
    __shared__ float vs[2][64];

    const int d = tid % 64;
    const int fg = tid / 64;         // f block: fg*16 .. fg*16+15

    float acc[16];
#pragma unroll
    for (int i = 0; i < 16; i++) acc[i] = 0.f;
    float ks = 0.f;

    const int n0 = chunk * 512;
    const int which = tid / 64;      // 0,1 -> kf rows; 2,3 -> v rows
    const int lane = tid % 64;
    const int rr = which % 2;

    for (int r = 0; r < 512; r += 2) {
        if (which < 2)
            kfs[rr][lane] = kf[((size_t)bh * N_ + n0 + r + rr) * 64 + lane];
        else
            vs[rr][lane] = v[((size_t)b * N_ + n0 + r + rr) * DIM_ + h * DH_ + lane];
        __syncthreads();
#pragma unroll
        for (int rr2 = 0; rr2 < 2; rr2++) {
            float vd = vs[rr2][d];
#pragma unroll
            for (int i = 0; i < 16; i++)
                acc[i] = fmaf(kfs[rr2][fg * 16 + i], vd, acc[i]);
            if (tid < 64) ks += kfs[rr2][tid];
        }
        __syncthreads();
    }

#pragma unroll
    for (int i = 0; i < 16; i++)
        atomicAdd(&g_kv[(size_t)bh * 4096 + (fg * 16 + i) * 64 + d], acc[i]);
    if (tid < 64) atomicAdd(&g_ksum[bh * 64 + tid], ks);
}

// ---------------- attn[b,n,h*64+d] = (qf @ kv) / (qf . ksum + EPS) ----------------
__global__ __launch_bounds__(256) void attn_out_kernel(
    const float* __restrict__ qf,    // [bh, n, 64]
    float* __restrict__ out)         // [b, n, 1024]
{
    const int bh = blockIdx.y;
    const int b = bh / H_, h = bh % H_;
    const int n0 = blockIdx.x * 64;
    const int tid = threadIdx.x;

    __shared__ float KV[64 * 64];
    __shared__ float KS[64];
    __shared__ float QF[64][65];

    for (int i = tid; i < 4096; i += 256) KV[i] = g_kv[(size_t)bh * 4096 + i];
    if (tid < 64) KS[tid] = g_ksum[bh * 64 + tid];
    for (int i = tid; i < 4096; i += 256) {
        int r = i / 64, f = i % 64;
        QF[r][f] = qf[((size_t)bh * N_ + n0 + r) * 64 + f];
    }
    __syncthreads();

    const int d = tid % 64;
    const int ry = tid / 64;
    for (int r = ry; r < 64; r += 4) {
        float num = 0.f, den = 0.f;
#pragma unroll
        for (int f = 0; f < 64; f++) {
            float q = QF[r][f];
            num = fmaf(q, KV[f * 64 + d], num);
            den = fmaf(q, KS[f], den);
        }
        out[((size_t)b * N_ + n0 + r) * DIM_ + h * DH_ + d] = num / (den + EPS);
    }
}

// ---------------- launch ----------------
extern "C" void kernel_launch(void* const* d_in, const int* in_sizes, int n_in,
                              void* d_out, int out_size)
{
    const float* x    = (const float*)d_in[0];
    const float* Wq   = (const float*)d_in[1];
    const float* Wk   = (const float*)d_in[2];
    const float* Wv   = (const float*)d_in[3];
    const float* proj = (const float*)d_in[4];
    const float* Wo   = (const float*)d_in[5];
    const float* bo   = (const float*)d_in[6];
    float* out = (float*)d_out;

    float *q, *k, *v, *qf, *kf, *attn;
    cudaGetSymbolAddress((void**)&q,    g_q);
    cudaGetSymbolAddress((void**)&k,    g_k);
    cudaGetSymbolAddress((void**)&v,    g_v);
    cudaGetSymbolAddress((void**)&qf,   g_qf);
    cudaGetSymbolAddress((void**)&kf,   g_kf);
    cudaGetSymbolAddress((void**)&attn, g_attn);

    dim3 gemm_grid(DIM_ / 128, M_ / 128);   // (8, 256)

    // QKV projections
    sgemm128<<<gemm_grid, 256>>>(x, Wq, q, M_, DIM_, DIM_, nullptr);
    sgemm128<<<gemm_grid, 256>>>(x, Wk, k, M_, DIM_, DIM_, nullptr);
    sgemm128<<<gemm_grid, 256>>>(x, Wv, v, M_, DIM_, DIM_, nullptr);

    // Feature maps
    dim3 fgrid(N_ / 64, B_ * H_);           // (128, 64)
    feature_map_kernel<<<fgrid, 256>>>(q, proj, qf);
    feature_map_kernel<<<fgrid, 256>>>(k, proj, kf);

    // kv + ksum reduction
    zero_kv_kernel<<<(64 * 64 * 64 + 255) / 256, 256>>>();
    kv_accum_kernel<<<dim3(16, B_ * H_), 256>>>(kf, v);

    // numerator / denominator
    attn_out_kernel<<<fgrid, 256>>>(qf, attn);

    // output projection + bias
    sgemm128<<<gemm_grid, 256>>>(attn, Wo, out, M_, DIM_, DIM_, bo);
}